// round 15
// baseline (speedup 1.0000x reference)
#include <cuda_runtime.h>
#include <cuda_bf16.h>
#include <math.h>
#include <stdint.h>

// Problem dims
#define BB 64
#define SS 512
#define II 512
#define HH 1024
#define OO 512
#define NBLK 128

// Scratch (device globals; no allocations)
__device__ float g_xi[SS * BB * HH];               // [s][b][h]
__device__ float g_hs[SS * BB * HH];               // fp32 (only t=SS-1 written)
__device__ __nv_bfloat16 g_hshi[SS * BB * HH];     // hs split hi
__device__ __nv_bfloat16 g_hslo[SS * BB * HH];     // hs split lo
__device__ __nv_bfloat16 g_xhi[BB * SS * II];
__device__ __nv_bfloat16 g_xlo[BB * SS * II];
__device__ __nv_bfloat16 g_Wihi[HH * II];
__device__ __nv_bfloat16 g_Wilo[HH * II];
__device__ __nv_bfloat16 g_Wohi[OO * HH];
__device__ __nv_bfloat16 g_Wolo[OO * HH];
__device__ unsigned g_wflags[NBLK * 8 * 32];       // per (cta,warp) flags

__global__ void reset_wflags_kernel()
{
    const int i = blockIdx.x * blockDim.x + threadIdx.x;   // [0,1024)
    g_wflags[i * 32] = 0u;
}

// ---------------------------------------------------------------------------
// helpers
// ---------------------------------------------------------------------------
__device__ __forceinline__ uint32_t smem_u32(const void* p) {
    return (uint32_t)__cvta_generic_to_shared(p);
}
__device__ __forceinline__ void mma16816(float d[4], const uint32_t a[4],
                                         const uint32_t b[2])
{
    asm volatile(
        "mma.sync.aligned.m16n8k16.row.col.f32.bf16.bf16.f32 "
        "{%0,%1,%2,%3}, {%4,%5,%6,%7}, {%8,%9}, {%0,%1,%2,%3};"
        : "+f"(d[0]), "+f"(d[1]), "+f"(d[2]), "+f"(d[3])
        : "r"(a[0]), "r"(a[1]), "r"(a[2]), "r"(a[3]), "r"(b[0]), "r"(b[1]));
}
__device__ __forceinline__ uint32_t pack_bf16(float f0, float f1)
{
    __nv_bfloat162 v;
    v.x = __float2bfloat16(f0);
    v.y = __float2bfloat16(f1);
    return *(uint32_t*)&v;
}

// ---------------------------------------------------------------------------
// fp32 -> (hi,lo) bf16 split kernels. WHICH: 0=x, 1=Wi, 2=Wo
// ---------------------------------------------------------------------------
template <int WHICH>
__global__ void split_kernel(const float* __restrict__ src)
{
    __nv_bfloat16* hi = (WHICH == 0) ? g_xhi : (WHICH == 1) ? g_Wihi : g_Wohi;
    __nv_bfloat16* lo = (WHICH == 0) ? g_xlo : (WHICH == 1) ? g_Wilo : g_Wolo;
    const int i = (blockIdx.x * blockDim.x + threadIdx.x) * 4;
    const float4 v = *(const float4*)(src + i);
    uint2 h, l;
    h.x = pack_bf16(v.x, v.y);
    h.y = pack_bf16(v.z, v.w);
    const __nv_bfloat162 p0 = *(const __nv_bfloat162*)&h.x;
    const __nv_bfloat162 p1 = *(const __nv_bfloat162*)&h.y;
    l.x = pack_bf16(v.x - __bfloat162float(p0.x), v.y - __bfloat162float(p0.y));
    l.y = pack_bf16(v.z - __bfloat162float(p1.x), v.w - __bfloat162float(p1.y));
    *(uint2*)(hi + i) = h;
    *(uint2*)(lo + i) = l;
}

// ---------------------------------------------------------------------------
// Tensor-core bf16x3 GEMM (3-stage pipeline, unchanged from R12)
// ---------------------------------------------------------------------------
#define GOFF_AH(st) ((st) * 65536 + 0)
#define GOFF_AL(st) ((st) * 65536 + 16384)
#define GOFF_BH(st) ((st) * 65536 + 32768)
#define GOFF_BL(st) ((st) * 65536 + 49152)
#define GEMM_SMEM 196608

__device__ __forceinline__ int swzg(int row, int kb) {
    return row * 128 + (kb ^ ((row & 7) << 4));
}

template <int MODE>
__global__ __launch_bounds__(256, 1)
void gemm_tc_kernel(const float* __restrict__ b1, const float* __restrict__ b2,
                    float* __restrict__ C, int K)
{
    extern __shared__ char smg[];
    const uint32_t smb = smem_u32(smg);
    const int tid = threadIdx.x;
    const int wid = tid >> 5;
    const int lane = tid & 31;
    const int g = lane >> 2;
    const int tig = lane & 3;
    const int m0 = blockIdx.x * 128;
    const int n0 = blockIdx.y * 128;
    const int wm = wid & 3;
    const int wn = wid >> 2;

    const __nv_bfloat16* Ah = (MODE == 0) ? g_xhi : g_hshi;
    const __nv_bfloat16* Al = (MODE == 0) ? g_xlo : g_hslo;
    const __nv_bfloat16* Bh = (MODE == 0) ? g_Wihi : g_Wohi;
    const __nv_bfloat16* Bl = (MODE == 0) ? g_Wilo : g_Wolo;

    const int lr0 = tid >> 3;
    const int kel = (tid & 7) * 8;

    float acc[2][8][4];
#pragma unroll
    for (int mt = 0; mt < 2; mt++)
#pragma unroll
        for (int nt = 0; nt < 8; nt++)
#pragma unroll
            for (int r = 0; r < 4; r++) acc[mt][nt][r] = 0.f;

    const int NC = K >> 6;

    auto load_chunk = [&](int st, int c) {
        const int kbase = c * 64 + kel;
#pragma unroll
        for (int i = 0; i < 4; i++) {
            const int row = lr0 + i * 32;
            const uint32_t sw = swzg(row, kel * 2);
            const void* sa_h = Ah + (size_t)(m0 + row) * K + kbase;
            const void* sa_l = Al + (size_t)(m0 + row) * K + kbase;
            const void* sb_h = Bh + (size_t)(n0 + row) * K + kbase;
            const void* sb_l = Bl + (size_t)(n0 + row) * K + kbase;
            asm volatile("cp.async.cg.shared.global [%0], [%1], 16;"
                         :: "r"(smb + GOFF_AH(st) + sw), "l"(sa_h));
            asm volatile("cp.async.cg.shared.global [%0], [%1], 16;"
                         :: "r"(smb + GOFF_AL(st) + sw), "l"(sa_l));
            asm volatile("cp.async.cg.shared.global [%0], [%1], 16;"
                         :: "r"(smb + GOFF_BH(st) + sw), "l"(sb_h));
            asm volatile("cp.async.cg.shared.global [%0], [%1], 16;"
                         :: "r"(smb + GOFF_BL(st) + sw), "l"(sb_l));
        }
    };

    load_chunk(0, 0);
    asm volatile("cp.async.commit_group;" ::: "memory");
    if (NC > 1) {
        load_chunk(1, 1);
        asm volatile("cp.async.commit_group;" ::: "memory");
    }

    int stc = 0;
    for (int c = 0; c < NC; c++) {
        if (c + 1 < NC) {
            asm volatile("cp.async.wait_group 1;" ::: "memory");
        } else {
            asm volatile("cp.async.wait_group 0;" ::: "memory");
        }
        __syncthreads();

        if (c + 2 < NC) {
            int stn = stc + 2;
            if (stn >= 3) stn -= 3;
            load_chunk(stn, c + 2);
            asm volatile("cp.async.commit_group;" ::: "memory");
        }

        const char* As_h = smg + GOFF_AH(stc);
        const char* As_l = smg + GOFF_AL(stc);
        const char* Bs_h = smg + GOFF_BH(stc);
        const char* Bs_l = smg + GOFF_BL(stc);

#pragma unroll
        for (int ks = 0; ks < 4; ks++) {
            const int kc = ks * 16 + tig * 2;
            uint32_t bhf[8][2], blf[8][2];
#pragma unroll
            for (int nt = 0; nt < 8; nt++) {
                const int rb = wn * 64 + nt * 8 + g;
                bhf[nt][0] = *(const uint32_t*)(Bs_h + swzg(rb, kc * 2));
                bhf[nt][1] = *(const uint32_t*)(Bs_h + swzg(rb, (kc + 8) * 2));
                blf[nt][0] = *(const uint32_t*)(Bs_l + swzg(rb, kc * 2));
                blf[nt][1] = *(const uint32_t*)(Bs_l + swzg(rb, (kc + 8) * 2));
            }
#pragma unroll
            for (int mt = 0; mt < 2; mt++) {
                uint32_t ah[4], al[4];
#pragma unroll
                for (int r = 0; r < 4; r++) {
                    const int rm = wm * 32 + mt * 16 + g + ((r & 1) ? 8 : 0);
                    const int kk = kc + ((r & 2) ? 8 : 0);
                    ah[r] = *(const uint32_t*)(As_h + swzg(rm, kk * 2));
                    al[r] = *(const uint32_t*)(As_l + swzg(rm, kk * 2));
                }
#pragma unroll
                for (int nt = 0; nt < 8; nt++) {
                    mma16816(acc[mt][nt], ah, bhf[nt]);
                    mma16816(acc[mt][nt], ah, blf[nt]);
                    mma16816(acc[mt][nt], al, bhf[nt]);
                }
            }
        }

        if (++stc == 3) stc = 0;
    }

#pragma unroll
    for (int mt = 0; mt < 2; mt++) {
#pragma unroll
        for (int r2 = 0; r2 < 2; r2++) {
            const int m = m0 + wm * 32 + mt * 16 + g + r2 * 8;
#pragma unroll
            for (int nt = 0; nt < 8; nt++) {
                const int n = n0 + wn * 64 + nt * 8 + tig * 2;
                float2 bias;
                bias.x = b1[n];
                bias.y = b1[n + 1];
                if (MODE == 0) { bias.x += b2[n]; bias.y += b2[n + 1]; }
                float2 v;
                v.x = acc[mt][nt][r2 * 2 + 0] + bias.x;
                v.y = acc[mt][nt][r2 * 2 + 1] + bias.y;
                if (MODE == 0) {
                    const int b = m >> 9, s = m & 511;
                    *(float2*)&g_xi[((size_t)s * 64 + b) * 1024 + n] = v;
                } else {
                    const int s = m >> 6, b = m & 63;
                    *(float2*)&C[((size_t)b * 512 + s) * 512 + n] = v;
                }
            }
        }
    }
}

// ---------------------------------------------------------------------------
// Persistent recurrence: R12 structure verbatim, except Wh_lo for mt 0,1
// lives in REGISTERS (cuts SMEM read traffic 16KB -> 8KB per warp per step;
// mainloop was smem-BW-bound per R14's evidence). Numerics identical.
// 8 groups of 16 CTAs. CTA (bt,jt): b [bt*8,+8), j [jt*64,+64).
// Warp wid owns k-slice [wid*128,+128).
// ---------------------------------------------------------------------------
#define OFF_WHL 0                        // 64 x 2048 B = 128 KB (mt 2,3 used)
#define OFF_STG 131072                   // 8 warps x 4 KB (2K hi + 2K lo)
#define OFF_RED 163840                   // 2 x 16 KB (double buffered)
#define RNN_SMEM_BYTES 196608

__device__ __forceinline__ int swz(int row, int kbyte) {
    return row * 2048 + (kbyte ^ ((row & 7) << 4));
}

__global__ __launch_bounds__(256, 1)
void rnn_persistent_kernel(const float* __restrict__ Wh)
{
    extern __shared__ char sm[];

    const int tid = threadIdx.x;
    const int wid = tid >> 5;
    const int lane = tid & 31;
    const int g = lane >> 2;
    const int tig = lane & 3;
    const int cta = blockIdx.x;
    const int jt = cta & 15;
    const int bt = cta >> 4;
    const int j0 = jt * 64;
    const int b0 = bt * 8;
    const int kw0 = wid * 128;
    const int grp0 = bt * 16;

    char* stgH = sm + OFF_STG + wid * 4096;       // warp-private hi (2 KB)
    char* stgL = stgH + 2048;                     // warp-private lo (2 KB)

    // one-time: Wh_hi -> regs; Wh_lo -> regs for mt 0,1 / smem for mt 2,3
    uint32_t a_hi[4][8][4];
    uint32_t a_lo[2][8][4];
#pragma unroll
    for (int mt = 0; mt < 4; mt++) {
#pragma unroll
        for (int ks = 0; ks < 8; ks++) {
#pragma unroll
            for (int r = 0; r < 4; r++) {
                const int jl = mt * 16 + g + ((r & 1) ? 8 : 0);
                const int k  = kw0 + ks * 16 + tig * 2 + ((r & 2) ? 8 : 0);
                const float2 w = *(const float2*)&Wh[(size_t)(j0 + jl) * HH + k];
                const uint32_t hi = pack_bf16(w.x, w.y);
                a_hi[mt][ks][r] = hi;
                const __nv_bfloat162 h2 = *(const __nv_bfloat162*)&hi;
                const uint32_t lo = pack_bf16(w.x - __bfloat162float(h2.x),
                                              w.y - __bfloat162float(h2.y));
                if (mt < 2) {
                    a_lo[mt][ks][r] = lo;
                } else {
                    *(uint32_t*)(sm + OFF_WHL + swz(jl, k * 2)) = lo;
                }
            }
        }
    }
    __syncthreads();

    for (int t = 0; t < SS; t++) {
        const int eb = wid;                 // this thread's output b (row)
        const int ej = lane * 2;            // output j pair
        const float2 xiv = *(const float2*)
            &g_xi[(size_t)t * BB * HH + (size_t)(b0 + eb) * HH + j0 + ej];

        float* red = (float*)(sm + OFF_RED + (t & 1) * 16384);

        float h0, h1;
        if (t > 0) {
            // per-warp poll: producers jt' = 2wid, 2wid+1 (8 warp-flags each)
            if (lane < 16) {
                const unsigned* fp =
                    &g_wflags[(((grp0 + 2 * wid + (lane >> 3)) << 3) + (lane & 7)) * 32];
                unsigned v;
                do {
                    asm volatile("ld.acquire.gpu.global.u32 %0, [%1];"
                                 : "=r"(v) : "l"(fp));
                } while (v < (unsigned)t);
            }
            __syncwarp();

            // warp-private staging of its own 8b x 128k hi/lo slice (4 KB)
            const __nv_bfloat16* srcH =
                g_hshi + (size_t)(t - 1) * BB * HH + (size_t)b0 * HH + kw0;
            const __nv_bfloat16* srcL =
                g_hslo + (size_t)(t - 1) * BB * HH + (size_t)b0 * HH + kw0;
#pragma unroll
            for (int i = 0; i < 4; i++) {
                const int u = i * 32 + lane;      // [0,128): 16B units
                const int row = u >> 4;
                const int c = u & 15;
                const uint4 vh = __ldcg((const uint4*)(srcH + row * HH + c * 8));
                const uint4 vl = __ldcg((const uint4*)(srcL + row * HH + c * 8));
                const int off = row * 256 + ((c * 16) ^ ((row & 7) << 4));
                *(uint4*)(stgH + off) = vh;
                *(uint4*)(stgL + off) = vl;
            }
            __syncwarp();

            // tensor-core mainloop
            float acc[4][4];
#pragma unroll
            for (int mt = 0; mt < 4; mt++)
#pragma unroll
                for (int r = 0; r < 4; r++) acc[mt][r] = 0.f;

#pragma unroll
            for (int ks = 0; ks < 8; ks++) {
                const int x0 = (ks * 32 + tig * 4) ^ ((g & 7) << 4);
                const int x1 = (ks * 32 + 16 + tig * 4) ^ ((g & 7) << 4);
                uint32_t bh[2], bl[2];
                bh[0] = *(const uint32_t*)(stgH + g * 256 + x0);
                bh[1] = *(const uint32_t*)(stgH + g * 256 + x1);
                bl[0] = *(const uint32_t*)(stgL + g * 256 + x0);
                bl[1] = *(const uint32_t*)(stgL + g * 256 + x1);
#pragma unroll
                for (int mt = 0; mt < 4; mt++)
                    mma16816(acc[mt], a_hi[mt][ks], bh);
#pragma unroll
                for (int mt = 0; mt < 4; mt++)
                    mma16816(acc[mt], a_hi[mt][ks], bl);
                // 3rd product: mt 0,1 from registers; mt 2,3 from SMEM
#pragma unroll
                for (int mt = 0; mt < 2; mt++)
                    mma16816(acc[mt], a_lo[mt][ks], bh);
#pragma unroll
                for (int mt = 2; mt < 4; mt++) {
                    uint32_t al[4];
#pragma unroll
                    for (int r = 0; r < 4; r++) {
                        const int jl = mt * 16 + g + ((r & 1) ? 8 : 0);
                        const int k  = kw0 + ks * 16 + tig * 2 + ((r & 2) ? 8 : 0);
                        al[r] = *(const uint32_t*)(sm + OFF_WHL + swz(jl, k * 2));
                    }
                    mma16816(acc[mt], al, bh);
                }
            }

            // cross-warp k-reduction (double-buffered scratch)
            float* rw = red + wid * 512;
#pragma unroll
            for (int mt = 0; mt < 4; mt++) {
                const int jl = mt * 16 + g;
                rw[(tig * 2) * 64 + jl]         = acc[mt][0];
                rw[(tig * 2 + 1) * 64 + jl]     = acc[mt][1];
                rw[(tig * 2) * 64 + jl + 8]     = acc[mt][2];
                rw[(tig * 2 + 1) * 64 + jl + 8] = acc[mt][3];
            }
            __syncthreads();          // the ONLY block sync per step

            const int e = tid * 2;
            float s0 = 0.f, s1 = 0.f;
#pragma unroll
            for (int w = 0; w < 8; w++) {
                const float2 v = *(const float2*)&red[w * 512 + e];
                s0 += v.x;
                s1 += v.y;
            }
            h0 = tanhf(s0 + xiv.x);
            h1 = tanhf(s1 + xiv.y);
        } else {
            h0 = tanhf(xiv.x);
            h1 = tanhf(xiv.y);
        }

        const size_t hoff = (size_t)t * BB * HH + (size_t)(b0 + eb) * HH + j0 + ej;
        const uint32_t ph = pack_bf16(h0, h1);
        const __nv_bfloat162 hv = *(const __nv_bfloat162*)&ph;
        const uint32_t pl = pack_bf16(h0 - __bfloat162float(hv.x),
                                      h1 - __bfloat162float(hv.y));
        *(uint32_t*)&g_hshi[hoff] = ph;
        *(uint32_t*)&g_hslo[hoff] = pl;
        if (t == SS - 1) {
            *(float2*)&g_hs[hoff] = make_float2(h0, h1);
        }

        if (t < SS - 1) {
            __syncwarp();             // this warp's h stores done
            if (lane == 0) {
                asm volatile("st.release.gpu.global.u32 [%0], %1;"
                             :: "l"(&g_wflags[((cta << 3) + wid) * 32]),
                                "r"((unsigned)(t + 1))
                             : "memory");
            }
        }
    }
}

__global__ void copy_hlast_kernel(float* __restrict__ dst)
{
    const int i = blockIdx.x * blockDim.x + threadIdx.x;
    dst[i] = g_hs[(size_t)(SS - 1) * BB * HH + i];
}

// ---------------------------------------------------------------------------
extern "C" void kernel_launch(void* const* d_in, const int* in_sizes, int n_in,
                              void* d_out, int out_size)
{
    const float* x  = (const float*)d_in[0];
    const float* Wi = (const float*)d_in[1];
    const float* bi = (const float*)d_in[2];
    const float* Wh = (const float*)d_in[3];
    const float* bh = (const float*)d_in[4];
    const float* Wo = (const float*)d_in[5];
    const float* bo = (const float*)d_in[6];
    float* out = (float*)d_out;

    cudaFuncSetAttribute(rnn_persistent_kernel,
                         cudaFuncAttributeMaxDynamicSharedMemorySize, RNN_SMEM_BYTES);
    cudaFuncSetAttribute(gemm_tc_kernel<0>,
                         cudaFuncAttributeMaxDynamicSharedMemorySize, GEMM_SMEM);
    cudaFuncSetAttribute(gemm_tc_kernel<1>,
                         cudaFuncAttributeMaxDynamicSharedMemorySize, GEMM_SMEM);

    // 0) fp32 -> bf16 hi/lo splits
    split_kernel<0><<<(BB * SS * II) / 1024, 256>>>(x);
    split_kernel<1><<<(HH * II) / 1024, 256>>>(Wi);
    split_kernel<2><<<(OO * HH) / 1024, 256>>>(Wo);

    // 1) xi = x @ Wi^T + bi + bh  (tensor core, 3-stage pipeline)
    dim3 g1((BB * SS) / 128, HH / 128);
    gemm_tc_kernel<0><<<g1, 256, GEMM_SMEM>>>(bi, bh, nullptr, II);

    // 2) recurrence (R12 structure, Wh_lo half-register)
    reset_wflags_kernel<<<4, 256>>>();
    rnn_persistent_kernel<<<NBLK, 256, RNN_SMEM_BYTES>>>(Wh);

    // 3) out = hs @ Wo^T + bo  (tensor core, 3-stage pipeline)
    dim3 g2((BB * SS) / 128, OO / 128);
    gemm_tc_kernel<1><<<g2, 256, GEMM_SMEM>>>(bo, nullptr, out, HH);

    // 4) h_last appended if expected
    if (out_size >= BB * SS * OO + BB * HH) {
        copy_hlast_kernel<<<(BB * HH) / 256, 256>>>(out + (size_t)BB * SS * OO);
    }
}

// round 16
// speedup vs baseline: 1.5463x; 1.5463x over previous
#include <cuda_runtime.h>
#include <cuda_bf16.h>
#include <cuda_fp16.h>
#include <math.h>
#include <stdint.h>

// Problem dims
#define BB 64
#define SS 512
#define II 512
#define HH 1024
#define OO 512
#define NBLK 128

// Scratch (device globals; no allocations)
__device__ float g_xi[SS * BB * HH];               // [s][b][h]
__device__ float g_hs[SS * BB * HH];               // fp32 (only t=SS-1 written)
__device__ __nv_bfloat16 g_hshi[SS * BB * HH];     // hs bf16 hi (out GEMM)
__device__ __nv_bfloat16 g_hslo[SS * BB * HH];     // hs bf16 lo
__device__ __half g_hfhi[SS * BB * HH];            // hs fp16 hi (recurrence)
__device__ __half g_hflo[SS * BB * HH];            // hs fp16 lo
__device__ __nv_bfloat16 g_xhi[BB * SS * II];
__device__ __nv_bfloat16 g_xlo[BB * SS * II];
__device__ __nv_bfloat16 g_Wihi[HH * II];
__device__ __nv_bfloat16 g_Wilo[HH * II];
__device__ __nv_bfloat16 g_Wohi[OO * HH];
__device__ __nv_bfloat16 g_Wolo[OO * HH];
__device__ unsigned g_wflags[NBLK * 8 * 32];       // per (cta,warp) flags

__global__ void reset_wflags_kernel()
{
    const int i = blockIdx.x * blockDim.x + threadIdx.x;   // [0,1024)
    g_wflags[i * 32] = 0u;
}

// ---------------------------------------------------------------------------
// helpers
// ---------------------------------------------------------------------------
__device__ __forceinline__ uint32_t smem_u32(const void* p) {
    return (uint32_t)__cvta_generic_to_shared(p);
}
__device__ __forceinline__ void mma16816(float d[4], const uint32_t a[4],
                                         const uint32_t b[2])
{
    asm volatile(
        "mma.sync.aligned.m16n8k16.row.col.f32.bf16.bf16.f32 "
        "{%0,%1,%2,%3}, {%4,%5,%6,%7}, {%8,%9}, {%0,%1,%2,%3};"
        : "+f"(d[0]), "+f"(d[1]), "+f"(d[2]), "+f"(d[3])
        : "r"(a[0]), "r"(a[1]), "r"(a[2]), "r"(a[3]), "r"(b[0]), "r"(b[1]));
}
__device__ __forceinline__ void mma16816h(float d[4], const uint32_t a[4],
                                          const uint32_t b[2])
{
    asm volatile(
        "mma.sync.aligned.m16n8k16.row.col.f32.f16.f16.f32 "
        "{%0,%1,%2,%3}, {%4,%5,%6,%7}, {%8,%9}, {%0,%1,%2,%3};"
        : "+f"(d[0]), "+f"(d[1]), "+f"(d[2]), "+f"(d[3])
        : "r"(a[0]), "r"(a[1]), "r"(a[2]), "r"(a[3]), "r"(b[0]), "r"(b[1]));
}
__device__ __forceinline__ uint32_t pack_bf16(float f0, float f1)
{
    __nv_bfloat162 v;
    v.x = __float2bfloat16(f0);
    v.y = __float2bfloat16(f1);
    return *(uint32_t*)&v;
}
__device__ __forceinline__ uint32_t pack_f16(float f0, float f1)
{
    const __half2 v = __floats2half2_rn(f0, f1);
    return *(const uint32_t*)&v;
}

// ---------------------------------------------------------------------------
// fp32 -> (hi,lo) bf16 split kernels. WHICH: 0=x, 1=Wi, 2=Wo
// ---------------------------------------------------------------------------
template <int WHICH>
__global__ void split_kernel(const float* __restrict__ src)
{
    __nv_bfloat16* hi = (WHICH == 0) ? g_xhi : (WHICH == 1) ? g_Wihi : g_Wohi;
    __nv_bfloat16* lo = (WHICH == 0) ? g_xlo : (WHICH == 1) ? g_Wilo : g_Wolo;
    const int i = (blockIdx.x * blockDim.x + threadIdx.x) * 4;
    const float4 v = *(const float4*)(src + i);
    uint2 h, l;
    h.x = pack_bf16(v.x, v.y);
    h.y = pack_bf16(v.z, v.w);
    const __nv_bfloat162 p0 = *(const __nv_bfloat162*)&h.x;
    const __nv_bfloat162 p1 = *(const __nv_bfloat162*)&h.y;
    l.x = pack_bf16(v.x - __bfloat162float(p0.x), v.y - __bfloat162float(p0.y));
    l.y = pack_bf16(v.z - __bfloat162float(p1.x), v.w - __bfloat162float(p1.y));
    *(uint2*)(hi + i) = h;
    *(uint2*)(lo + i) = l;
}

// ---------------------------------------------------------------------------
// Tensor-core bf16x3 GEMM (3-stage pipeline, unchanged from R12)
// ---------------------------------------------------------------------------
#define GOFF_AH(st) ((st) * 65536 + 0)
#define GOFF_AL(st) ((st) * 65536 + 16384)
#define GOFF_BH(st) ((st) * 65536 + 32768)
#define GOFF_BL(st) ((st) * 65536 + 49152)
#define GEMM_SMEM 196608

__device__ __forceinline__ int swzg(int row, int kb) {
    return row * 128 + (kb ^ ((row & 7) << 4));
}

template <int MODE>
__global__ __launch_bounds__(256, 1)
void gemm_tc_kernel(const float* __restrict__ b1, const float* __restrict__ b2,
                    float* __restrict__ C, int K)
{
    extern __shared__ char smg[];
    const uint32_t smb = smem_u32(smg);
    const int tid = threadIdx.x;
    const int wid = tid >> 5;
    const int lane = tid & 31;
    const int g = lane >> 2;
    const int tig = lane & 3;
    const int m0 = blockIdx.x * 128;
    const int n0 = blockIdx.y * 128;
    const int wm = wid & 3;
    const int wn = wid >> 2;

    const __nv_bfloat16* Ah = (MODE == 0) ? g_xhi : g_hshi;
    const __nv_bfloat16* Al = (MODE == 0) ? g_xlo : g_hslo;
    const __nv_bfloat16* Bh = (MODE == 0) ? g_Wihi : g_Wohi;
    const __nv_bfloat16* Bl = (MODE == 0) ? g_Wilo : g_Wolo;

    const int lr0 = tid >> 3;
    const int kel = (tid & 7) * 8;

    float acc[2][8][4];
#pragma unroll
    for (int mt = 0; mt < 2; mt++)
#pragma unroll
        for (int nt = 0; nt < 8; nt++)
#pragma unroll
            for (int r = 0; r < 4; r++) acc[mt][nt][r] = 0.f;

    const int NC = K >> 6;

    auto load_chunk = [&](int st, int c) {
        const int kbase = c * 64 + kel;
#pragma unroll
        for (int i = 0; i < 4; i++) {
            const int row = lr0 + i * 32;
            const uint32_t sw = swzg(row, kel * 2);
            const void* sa_h = Ah + (size_t)(m0 + row) * K + kbase;
            const void* sa_l = Al + (size_t)(m0 + row) * K + kbase;
            const void* sb_h = Bh + (size_t)(n0 + row) * K + kbase;
            const void* sb_l = Bl + (size_t)(n0 + row) * K + kbase;
            asm volatile("cp.async.cg.shared.global [%0], [%1], 16;"
                         :: "r"(smb + GOFF_AH(st) + sw), "l"(sa_h));
            asm volatile("cp.async.cg.shared.global [%0], [%1], 16;"
                         :: "r"(smb + GOFF_AL(st) + sw), "l"(sa_l));
            asm volatile("cp.async.cg.shared.global [%0], [%1], 16;"
                         :: "r"(smb + GOFF_BH(st) + sw), "l"(sb_h));
            asm volatile("cp.async.cg.shared.global [%0], [%1], 16;"
                         :: "r"(smb + GOFF_BL(st) + sw), "l"(sb_l));
        }
    };

    load_chunk(0, 0);
    asm volatile("cp.async.commit_group;" ::: "memory");
    if (NC > 1) {
        load_chunk(1, 1);
        asm volatile("cp.async.commit_group;" ::: "memory");
    }

    int stc = 0;
    for (int c = 0; c < NC; c++) {
        if (c + 1 < NC) {
            asm volatile("cp.async.wait_group 1;" ::: "memory");
        } else {
            asm volatile("cp.async.wait_group 0;" ::: "memory");
        }
        __syncthreads();

        if (c + 2 < NC) {
            int stn = stc + 2;
            if (stn >= 3) stn -= 3;
            load_chunk(stn, c + 2);
            asm volatile("cp.async.commit_group;" ::: "memory");
        }

        const char* As_h = smg + GOFF_AH(stc);
        const char* As_l = smg + GOFF_AL(stc);
        const char* Bs_h = smg + GOFF_BH(stc);
        const char* Bs_l = smg + GOFF_BL(stc);

#pragma unroll
        for (int ks = 0; ks < 4; ks++) {
            const int kc = ks * 16 + tig * 2;
            uint32_t bhf[8][2], blf[8][2];
#pragma unroll
            for (int nt = 0; nt < 8; nt++) {
                const int rb = wn * 64 + nt * 8 + g;
                bhf[nt][0] = *(const uint32_t*)(Bs_h + swzg(rb, kc * 2));
                bhf[nt][1] = *(const uint32_t*)(Bs_h + swzg(rb, (kc + 8) * 2));
                blf[nt][0] = *(const uint32_t*)(Bs_l + swzg(rb, kc * 2));
                blf[nt][1] = *(const uint32_t*)(Bs_l + swzg(rb, (kc + 8) * 2));
            }
#pragma unroll
            for (int mt = 0; mt < 2; mt++) {
                uint32_t ah[4], al[4];
#pragma unroll
                for (int r = 0; r < 4; r++) {
                    const int rm = wm * 32 + mt * 16 + g + ((r & 1) ? 8 : 0);
                    const int kk = kc + ((r & 2) ? 8 : 0);
                    ah[r] = *(const uint32_t*)(As_h + swzg(rm, kk * 2));
                    al[r] = *(const uint32_t*)(As_l + swzg(rm, kk * 2));
                }
#pragma unroll
                for (int nt = 0; nt < 8; nt++) {
                    mma16816(acc[mt][nt], ah, bhf[nt]);
                    mma16816(acc[mt][nt], ah, blf[nt]);
                    mma16816(acc[mt][nt], al, bhf[nt]);
                }
            }
        }

        if (++stc == 3) stc = 0;
    }

#pragma unroll
    for (int mt = 0; mt < 2; mt++) {
#pragma unroll
        for (int r2 = 0; r2 < 2; r2++) {
            const int m = m0 + wm * 32 + mt * 16 + g + r2 * 8;
#pragma unroll
            for (int nt = 0; nt < 8; nt++) {
                const int n = n0 + wn * 64 + nt * 8 + tig * 2;
                float2 bias;
                bias.x = b1[n];
                bias.y = b1[n + 1];
                if (MODE == 0) { bias.x += b2[n]; bias.y += b2[n + 1]; }
                float2 v;
                v.x = acc[mt][nt][r2 * 2 + 0] + bias.x;
                v.y = acc[mt][nt][r2 * 2 + 1] + bias.y;
                if (MODE == 0) {
                    const int b = m >> 9, s = m & 511;
                    *(float2*)&g_xi[((size_t)s * 64 + b) * 1024 + n] = v;
                } else {
                    const int s = m >> 6, b = m & 63;
                    *(float2*)&C[((size_t)b * 512 + s) * 512 + n] = v;
                }
            }
        }
    }
}

// ---------------------------------------------------------------------------
// Persistent recurrence: R12 structure, fp16x2 split (NO Wh_lo array).
// preact = Whi(fp16)*hhi(fp16) + Whi*hlo; dropped Wlo*hhi ~2^-12 rel.
// 8 groups of 16 CTAs. CTA (bt,jt): b [bt*8,+8), j [jt*64,+64).
// Warp wid owns k-slice [wid*128,+128); producers jt'=2wid,2wid+1.
// Per-warp poll + warp-private staging + per-warp release; 1 syncthreads.
// ---------------------------------------------------------------------------
#define OFF_STG 0                        // 8 warps x 4 KB (2K hi + 2K lo)
#define OFF_RED 32768                    // 2 x 16 KB (double buffered)
#define RNN_SMEM_BYTES 65536

__global__ __launch_bounds__(256, 1)
void rnn_persistent_kernel(const float* __restrict__ Wh)
{
    extern __shared__ char sm[];

    const int tid = threadIdx.x;
    const int wid = tid >> 5;
    const int lane = tid & 31;
    const int g = lane >> 2;
    const int tig = lane & 3;
    const int cta = blockIdx.x;
    const int jt = cta & 15;
    const int bt = cta >> 4;
    const int j0 = jt * 64;
    const int b0 = bt * 8;
    const int kw0 = wid * 128;
    const int grp0 = bt * 16;

    char* stgH = sm + OFF_STG + wid * 4096;       // warp-private hi (2 KB)
    char* stgL = stgH + 2048;                     // warp-private lo (2 KB)

    // one-time: Wh_hi (fp16) -> regs
    uint32_t a_hi[4][8][4];
#pragma unroll
    for (int mt = 0; mt < 4; mt++) {
#pragma unroll
        for (int ks = 0; ks < 8; ks++) {
#pragma unroll
            for (int r = 0; r < 4; r++) {
                const int jl = mt * 16 + g + ((r & 1) ? 8 : 0);
                const int k  = kw0 + ks * 16 + tig * 2 + ((r & 2) ? 8 : 0);
                const float2 w = *(const float2*)&Wh[(size_t)(j0 + jl) * HH + k];
                a_hi[mt][ks][r] = pack_f16(w.x, w.y);
            }
        }
    }
    __syncthreads();

    for (int t = 0; t < SS; t++) {
        const int eb = wid;                 // this thread's output b (row)
        const int ej = lane * 2;            // output j pair
        const float2 xiv = *(const float2*)
            &g_xi[(size_t)t * BB * HH + (size_t)(b0 + eb) * HH + j0 + ej];

        float* red = (float*)(sm + OFF_RED + (t & 1) * 16384);

        float h0, h1;
        if (t > 0) {
            // per-warp poll: producers jt' = 2wid, 2wid+1 (8 warp-flags each)
            if (lane < 16) {
                const unsigned* fp =
                    &g_wflags[(((grp0 + 2 * wid + (lane >> 3)) << 3) + (lane & 7)) * 32];
                unsigned v;
                do {
                    asm volatile("ld.acquire.gpu.global.u32 %0, [%1];"
                                 : "=r"(v) : "l"(fp));
                } while (v < (unsigned)t);
            }
            __syncwarp();

            // warp-private staging of its own 8b x 128k fp16 hi/lo (4 KB)
            const __half* srcH =
                g_hfhi + (size_t)(t - 1) * BB * HH + (size_t)b0 * HH + kw0;
            const __half* srcL =
                g_hflo + (size_t)(t - 1) * BB * HH + (size_t)b0 * HH + kw0;
#pragma unroll
            for (int i = 0; i < 4; i++) {
                const int u = i * 32 + lane;      // [0,128): 16B units
                const int row = u >> 4;
                const int c = u & 15;
                const uint4 vh = __ldcg((const uint4*)(srcH + row * HH + c * 8));
                const uint4 vl = __ldcg((const uint4*)(srcL + row * HH + c * 8));
                const int off = row * 256 + ((c * 16) ^ ((row & 7) << 4));
                *(uint4*)(stgH + off) = vh;
                *(uint4*)(stgL + off) = vl;
            }
            __syncwarp();

            // tensor-core mainloop: 2 products, fp16
            float acc[4][4];
#pragma unroll
            for (int mt = 0; mt < 4; mt++)
#pragma unroll
                for (int r = 0; r < 4; r++) acc[mt][r] = 0.f;

#pragma unroll
            for (int ks = 0; ks < 8; ks++) {
                const int x0 = (ks * 32 + tig * 4) ^ ((g & 7) << 4);
                const int x1 = (ks * 32 + 16 + tig * 4) ^ ((g & 7) << 4);
                uint32_t bh[2], bl[2];
                bh[0] = *(const uint32_t*)(stgH + g * 256 + x0);
                bh[1] = *(const uint32_t*)(stgH + g * 256 + x1);
                bl[0] = *(const uint32_t*)(stgL + g * 256 + x0);
                bl[1] = *(const uint32_t*)(stgL + g * 256 + x1);
#pragma unroll
                for (int mt = 0; mt < 4; mt++)
                    mma16816h(acc[mt], a_hi[mt][ks], bh);
#pragma unroll
                for (int mt = 0; mt < 4; mt++)
                    mma16816h(acc[mt], a_hi[mt][ks], bl);
            }

            // cross-warp k-reduction (double-buffered scratch)
            float* rw = red + wid * 512;
#pragma unroll
            for (int mt = 0; mt < 4; mt++) {
                const int jl = mt * 16 + g;
                rw[(tig * 2) * 64 + jl]         = acc[mt][0];
                rw[(tig * 2 + 1) * 64 + jl]     = acc[mt][1];
                rw[(tig * 2) * 64 + jl + 8]     = acc[mt][2];
                rw[(tig * 2 + 1) * 64 + jl + 8] = acc[mt][3];
            }
            __syncthreads();          // the ONLY block sync per step

            const int e = tid * 2;
            float s0 = 0.f, s1 = 0.f;
#pragma unroll
            for (int w = 0; w < 8; w++) {
                const float2 v = *(const float2*)&red[w * 512 + e];
                s0 += v.x;
                s1 += v.y;
            }
            h0 = tanhf(s0 + xiv.x);
            h1 = tanhf(s1 + xiv.y);
        } else {
            h0 = tanhf(xiv.x);
            h1 = tanhf(xiv.y);
        }

        const size_t hoff = (size_t)t * BB * HH + (size_t)(b0 + eb) * HH + j0 + ej;
        // bf16 split for the output GEMM
        const uint32_t ph = pack_bf16(h0, h1);
        const __nv_bfloat162 hv = *(const __nv_bfloat162*)&ph;
        const uint32_t pl = pack_bf16(h0 - __bfloat162float(hv.x),
                                      h1 - __bfloat162float(hv.y));
        *(uint32_t*)&g_hshi[hoff] = ph;
        *(uint32_t*)&g_hslo[hoff] = pl;
        // fp16 split for the next recurrence step
        const uint32_t fh = pack_f16(h0, h1);
        const __half2 fhv = *(const __half2*)&fh;
        const uint32_t fl = pack_f16(h0 - __half2float(fhv.x),
                                     h1 - __half2float(fhv.y));
        *(uint32_t*)&g_hfhi[hoff] = fh;
        *(uint32_t*)&g_hflo[hoff] = fl;
        if (t == SS - 1) {
            *(float2*)&g_hs[hoff] = make_float2(h0, h1);
        }

        if (t < SS - 1) {
            __syncwarp();             // this warp's h stores done
            if (lane == 0) {
                asm volatile("st.release.gpu.global.u32 [%0], %1;"
                             :: "l"(&g_wflags[((cta << 3) + wid) * 32]),
                                "r"((unsigned)(t + 1))
                             : "memory");
            }
        }
    }
}

__global__ void copy_hlast_kernel(float* __restrict__ dst)
{
    const int i = blockIdx.x * blockDim.x + threadIdx.x;
    dst[i] = g_hs[(size_t)(SS - 1) * BB * HH + i];
}

// ---------------------------------------------------------------------------
extern "C" void kernel_launch(void* const* d_in, const int* in_sizes, int n_in,
                              void* d_out, int out_size)
{
    const float* x  = (const float*)d_in[0];
    const float* Wi = (const float*)d_in[1];
    const float* bi = (const float*)d_in[2];
    const float* Wh = (const float*)d_in[3];
    const float* bh = (const float*)d_in[4];
    const float* Wo = (const float*)d_in[5];
    const float* bo = (const float*)d_in[6];
    float* out = (float*)d_out;

    cudaFuncSetAttribute(rnn_persistent_kernel,
                         cudaFuncAttributeMaxDynamicSharedMemorySize, RNN_SMEM_BYTES);
    cudaFuncSetAttribute(gemm_tc_kernel<0>,
                         cudaFuncAttributeMaxDynamicSharedMemorySize, GEMM_SMEM);
    cudaFuncSetAttribute(gemm_tc_kernel<1>,
                         cudaFuncAttributeMaxDynamicSharedMemorySize, GEMM_SMEM);

    // 0) fp32 -> bf16 hi/lo splits
    split_kernel<0><<<(BB * SS * II) / 1024, 256>>>(x);
    split_kernel<1><<<(HH * II) / 1024, 256>>>(Wi);
    split_kernel<2><<<(OO * HH) / 1024, 256>>>(Wo);

    // 1) xi = x @ Wi^T + bi + bh  (tensor core, 3-stage pipeline)
    dim3 g1((BB * SS) / 128, HH / 128);
    gemm_tc_kernel<0><<<g1, 256, GEMM_SMEM>>>(bi, bh, nullptr, II);

    // 2) recurrence (fp16x2 persistent)
    reset_wflags_kernel<<<4, 256>>>();
    rnn_persistent_kernel<<<NBLK, 256, RNN_SMEM_BYTES>>>(Wh);

    // 3) out = hs @ Wo^T + bo  (tensor core, 3-stage pipeline)
    dim3 g2((BB * SS) / 128, OO / 128);
    gemm_tc_kernel<1><<<g2, 256, GEMM_SMEM>>>(bo, nullptr, out, HH);

    // 4) h_last appended if expected
    if (out_size >= BB * SS * OO + BB * HH) {
        copy_hlast_kernel<<<(BB * HH) / 256, 256>>>(out + (size_t)BB * SS * OO);
    }
}

// round 17
// speedup vs baseline: 1.7004x; 1.0997x over previous
#include <cuda_runtime.h>
#include <cuda_bf16.h>
#include <cuda_fp16.h>
#include <math.h>
#include <stdint.h>

// Problem dims
#define BB 64
#define SS 512
#define II 512
#define HH 1024
#define OO 512
#define NBLK 128

// Scratch (device globals; no allocations)
__device__ float g_xi[SS * BB * HH];               // [s][b][h]
__device__ float g_hs[SS * BB * HH];               // fp32 (only t=SS-1 written)
__device__ __half g_hfhi[SS * BB * HH];            // hs fp16 hi
__device__ __half g_hflo[SS * BB * HH];            // hs fp16 lo
__device__ __half g_xfhi[BB * SS * II];            // x fp16 hi
__device__ __half g_xflo[BB * SS * II];            // x fp16 lo
__device__ __half g_Wih[HH * II];                  // Wi fp16 (hi only)
__device__ __half g_Woh[OO * HH];                  // Wo fp16 (hi only)
__device__ unsigned g_wflags[NBLK * 8 * 32];       // per (cta,warp) flags

__global__ void reset_wflags_kernel()
{
    const int i = blockIdx.x * blockDim.x + threadIdx.x;   // [0,1024)
    g_wflags[i * 32] = 0u;
}

// ---------------------------------------------------------------------------
// helpers
// ---------------------------------------------------------------------------
__device__ __forceinline__ uint32_t smem_u32(const void* p) {
    return (uint32_t)__cvta_generic_to_shared(p);
}
__device__ __forceinline__ void mma16816h(float d[4], const uint32_t a[4],
                                          const uint32_t b[2])
{
    asm volatile(
        "mma.sync.aligned.m16n8k16.row.col.f32.f16.f16.f32 "
        "{%0,%1,%2,%3}, {%4,%5,%6,%7}, {%8,%9}, {%0,%1,%2,%3};"
        : "+f"(d[0]), "+f"(d[1]), "+f"(d[2]), "+f"(d[3])
        : "r"(a[0]), "r"(a[1]), "r"(a[2]), "r"(a[3]), "r"(b[0]), "r"(b[1]));
}
__device__ __forceinline__ uint32_t pack_f16(float f0, float f1)
{
    const __half2 v = __floats2half2_rn(f0, f1);
    return *(const uint32_t*)&v;
}

// ---------------------------------------------------------------------------
// x: fp32 -> fp16 (hi, lo) split
// ---------------------------------------------------------------------------
__global__ void splitx_kernel(const float* __restrict__ src)
{
    const int i = (blockIdx.x * blockDim.x + threadIdx.x) * 4;
    const float4 v = *(const float4*)(src + i);
    uint2 h;
    h.x = pack_f16(v.x, v.y);
    h.y = pack_f16(v.z, v.w);
    const __half2 p0 = *(const __half2*)&h.x;
    const __half2 p1 = *(const __half2*)&h.y;
    uint2 l;
    l.x = pack_f16(v.x - __half2float(p0.x), v.y - __half2float(p0.y));
    l.y = pack_f16(v.z - __half2float(p1.x), v.w - __half2float(p1.y));
    *(uint2*)(g_xfhi + i) = h;
    *(uint2*)(g_xflo + i) = l;
}

// Wi / Wo: fp32 -> fp16 (hi only). WHICH: 1=Wi, 2=Wo
template <int WHICH>
__global__ void splitw_kernel(const float* __restrict__ src)
{
    __half* hi = (WHICH == 1) ? g_Wih : g_Woh;
    const int i = (blockIdx.x * blockDim.x + threadIdx.x) * 4;
    const float4 v = *(const float4*)(src + i);
    uint2 h;
    h.x = pack_f16(v.x, v.y);
    h.y = pack_f16(v.z, v.w);
    *(uint2*)(hi + i) = h;
}

// ---------------------------------------------------------------------------
// Tensor-core fp16x2 GEMM: C = A(MxK) * B(NxK)^T + bias (fp32 accum)
// A = hi+lo fp16 split (correction on activation side), B = fp16 hi only.
// 3-stage cp.async pipeline, tile 128x128x64, 8 warps.
// MODE 0: A = x split, B = Wi, write g_xi[s][b][n], m=b*512+s, bias=b1+b2
// MODE 1: A = hs split, B = Wo, write C[b][s][n], m=s*64+b, bias=b1
// ---------------------------------------------------------------------------
#define GOFF_AH(st) ((st) * 49152 + 0)
#define GOFF_AL(st) ((st) * 49152 + 16384)
#define GOFF_BH(st) ((st) * 49152 + 32768)
#define GEMM_SMEM 147456

__device__ __forceinline__ int swzg(int row, int kb) {
    return row * 128 + (kb ^ ((row & 7) << 4));
}

template <int MODE>
__global__ __launch_bounds__(256, 1)
void gemm_tc_kernel(const float* __restrict__ b1, const float* __restrict__ b2,
                    float* __restrict__ C, int K)
{
    extern __shared__ char smg[];
    const uint32_t smb = smem_u32(smg);
    const int tid = threadIdx.x;
    const int wid = tid >> 5;
    const int lane = tid & 31;
    const int g = lane >> 2;
    const int tig = lane & 3;
    const int m0 = blockIdx.x * 128;
    const int n0 = blockIdx.y * 128;
    const int wm = wid & 3;
    const int wn = wid >> 2;

    const __half* Ah = (MODE == 0) ? g_xfhi : g_hfhi;
    const __half* Al = (MODE == 0) ? g_xflo : g_hflo;
    const __half* Bh = (MODE == 0) ? g_Wih : g_Woh;

    const int lr0 = tid >> 3;
    const int kel = (tid & 7) * 8;

    float acc[2][8][4];
#pragma unroll
    for (int mt = 0; mt < 2; mt++)
#pragma unroll
        for (int nt = 0; nt < 8; nt++)
#pragma unroll
            for (int r = 0; r < 4; r++) acc[mt][nt][r] = 0.f;

    const int NC = K >> 6;

    auto load_chunk = [&](int st, int c) {
        const int kbase = c * 64 + kel;
#pragma unroll
        for (int i = 0; i < 4; i++) {
            const int row = lr0 + i * 32;
            const uint32_t sw = swzg(row, kel * 2);
            const void* sa_h = Ah + (size_t)(m0 + row) * K + kbase;
            const void* sa_l = Al + (size_t)(m0 + row) * K + kbase;
            const void* sb_h = Bh + (size_t)(n0 + row) * K + kbase;
            asm volatile("cp.async.cg.shared.global [%0], [%1], 16;"
                         :: "r"(smb + GOFF_AH(st) + sw), "l"(sa_h));
            asm volatile("cp.async.cg.shared.global [%0], [%1], 16;"
                         :: "r"(smb + GOFF_AL(st) + sw), "l"(sa_l));
            asm volatile("cp.async.cg.shared.global [%0], [%1], 16;"
                         :: "r"(smb + GOFF_BH(st) + sw), "l"(sb_h));
        }
    };

    load_chunk(0, 0);
    asm volatile("cp.async.commit_group;" ::: "memory");
    if (NC > 1) {
        load_chunk(1, 1);
        asm volatile("cp.async.commit_group;" ::: "memory");
    }

    int stc = 0;
    for (int c = 0; c < NC; c++) {
        if (c + 1 < NC) {
            asm volatile("cp.async.wait_group 1;" ::: "memory");
        } else {
            asm volatile("cp.async.wait_group 0;" ::: "memory");
        }
        __syncthreads();

        if (c + 2 < NC) {
            int stn = stc + 2;
            if (stn >= 3) stn -= 3;
            load_chunk(stn, c + 2);
            asm volatile("cp.async.commit_group;" ::: "memory");
        }

        const char* As_h = smg + GOFF_AH(stc);
        const char* As_l = smg + GOFF_AL(stc);
        const char* Bs_h = smg + GOFF_BH(stc);

#pragma unroll
        for (int ks = 0; ks < 4; ks++) {
            const int kc = ks * 16 + tig * 2;
            uint32_t bhf[8][2];
#pragma unroll
            for (int nt = 0; nt < 8; nt++) {
                const int rb = wn * 64 + nt * 8 + g;
                bhf[nt][0] = *(const uint32_t*)(Bs_h + swzg(rb, kc * 2));
                bhf[nt][1] = *(const uint32_t*)(Bs_h + swzg(rb, (kc + 8) * 2));
            }
#pragma unroll
            for (int mt = 0; mt < 2; mt++) {
                uint32_t ah[4], al[4];
#pragma unroll
                for (int r = 0; r < 4; r++) {
                    const int rm = wm * 32 + mt * 16 + g + ((r & 1) ? 8 : 0);
                    const int kk = kc + ((r & 2) ? 8 : 0);
                    ah[r] = *(const uint32_t*)(As_h + swzg(rm, kk * 2));
                    al[r] = *(const uint32_t*)(As_l + swzg(rm, kk * 2));
                }
#pragma unroll
                for (int nt = 0; nt < 8; nt++) {
                    mma16816h(acc[mt][nt], ah, bhf[nt]);
                    mma16816h(acc[mt][nt], al, bhf[nt]);
                }
            }
        }

        if (++stc == 3) stc = 0;
    }

#pragma unroll
    for (int mt = 0; mt < 2; mt++) {
#pragma unroll
        for (int r2 = 0; r2 < 2; r2++) {
            const int m = m0 + wm * 32 + mt * 16 + g + r2 * 8;
#pragma unroll
            for (int nt = 0; nt < 8; nt++) {
                const int n = n0 + wn * 64 + nt * 8 + tig * 2;
                float2 bias;
                bias.x = b1[n];
                bias.y = b1[n + 1];
                if (MODE == 0) { bias.x += b2[n]; bias.y += b2[n + 1]; }
                float2 v;
                v.x = acc[mt][nt][r2 * 2 + 0] + bias.x;
                v.y = acc[mt][nt][r2 * 2 + 1] + bias.y;
                if (MODE == 0) {
                    const int b = m >> 9, s = m & 511;
                    *(float2*)&g_xi[((size_t)s * 64 + b) * 1024 + n] = v;
                } else {
                    const int s = m >> 6, b = m & 63;
                    *(float2*)&C[((size_t)b * 512 + s) * 512 + n] = v;
                }
            }
        }
    }
}

// ---------------------------------------------------------------------------
// Persistent recurrence: fp16x2 (R16 config, minus bf16 epilogue writes).
// 8 groups of 16 CTAs. CTA (bt,jt): b [bt*8,+8), j [jt*64,+64).
// Warp wid owns k-slice [wid*128,+128); producers jt'=2wid,2wid+1.
// ---------------------------------------------------------------------------
#define OFF_STG 0                        // 8 warps x 4 KB (2K hi + 2K lo)
#define OFF_RED 32768                    // 2 x 16 KB (double buffered)
#define RNN_SMEM_BYTES 65536

__global__ __launch_bounds__(256, 1)
void rnn_persistent_kernel(const float* __restrict__ Wh)
{
    extern __shared__ char sm[];

    const int tid = threadIdx.x;
    const int wid = tid >> 5;
    const int lane = tid & 31;
    const int g = lane >> 2;
    const int tig = lane & 3;
    const int cta = blockIdx.x;
    const int jt = cta & 15;
    const int bt = cta >> 4;
    const int j0 = jt * 64;
    const int b0 = bt * 8;
    const int kw0 = wid * 128;
    const int grp0 = bt * 16;

    char* stgH = sm + OFF_STG + wid * 4096;       // warp-private hi (2 KB)
    char* stgL = stgH + 2048;                     // warp-private lo (2 KB)

    // one-time: Wh_hi (fp16) -> regs
    uint32_t a_hi[4][8][4];
#pragma unroll
    for (int mt = 0; mt < 4; mt++) {
#pragma unroll
        for (int ks = 0; ks < 8; ks++) {
#pragma unroll
            for (int r = 0; r < 4; r++) {
                const int jl = mt * 16 + g + ((r & 1) ? 8 : 0);
                const int k  = kw0 + ks * 16 + tig * 2 + ((r & 2) ? 8 : 0);
                const float2 w = *(const float2*)&Wh[(size_t)(j0 + jl) * HH + k];
                a_hi[mt][ks][r] = pack_f16(w.x, w.y);
            }
        }
    }
    __syncthreads();

    for (int t = 0; t < SS; t++) {
        const int eb = wid;                 // this thread's output b (row)
        const int ej = lane * 2;            // output j pair
        const float2 xiv = *(const float2*)
            &g_xi[(size_t)t * BB * HH + (size_t)(b0 + eb) * HH + j0 + ej];

        float* red = (float*)(sm + OFF_RED + (t & 1) * 16384);

        float h0, h1;
        if (t > 0) {
            // per-warp poll: producers jt' = 2wid, 2wid+1 (8 warp-flags each)
            if (lane < 16) {
                const unsigned* fp =
                    &g_wflags[(((grp0 + 2 * wid + (lane >> 3)) << 3) + (lane & 7)) * 32];
                unsigned v;
                do {
                    asm volatile("ld.acquire.gpu.global.u32 %0, [%1];"
                                 : "=r"(v) : "l"(fp));
                } while (v < (unsigned)t);
            }
            __syncwarp();

            // warp-private staging of its own 8b x 128k fp16 hi/lo (4 KB)
            const __half* srcH =
                g_hfhi + (size_t)(t - 1) * BB * HH + (size_t)b0 * HH + kw0;
            const __half* srcL =
                g_hflo + (size_t)(t - 1) * BB * HH + (size_t)b0 * HH + kw0;
#pragma unroll
            for (int i = 0; i < 4; i++) {
                const int u = i * 32 + lane;      // [0,128): 16B units
                const int row = u >> 4;
                const int c = u & 15;
                const uint4 vh = __ldcg((const uint4*)(srcH + row * HH + c * 8));
                const uint4 vl = __ldcg((const uint4*)(srcL + row * HH + c * 8));
                const int off = row * 256 + ((c * 16) ^ ((row & 7) << 4));
                *(uint4*)(stgH + off) = vh;
                *(uint4*)(stgL + off) = vl;
            }
            __syncwarp();

            // tensor-core mainloop: 2 products, fp16
            float acc[4][4];
#pragma unroll
            for (int mt = 0; mt < 4; mt++)
#pragma unroll
                for (int r = 0; r < 4; r++) acc[mt][r] = 0.f;

#pragma unroll
            for (int ks = 0; ks < 8; ks++) {
                const int x0 = (ks * 32 + tig * 4) ^ ((g & 7) << 4);
                const int x1 = (ks * 32 + 16 + tig * 4) ^ ((g & 7) << 4);
                uint32_t bh[2], bl[2];
                bh[0] = *(const uint32_t*)(stgH + g * 256 + x0);
                bh[1] = *(const uint32_t*)(stgH + g * 256 + x1);
                bl[0] = *(const uint32_t*)(stgL + g * 256 + x0);
                bl[1] = *(const uint32_t*)(stgL + g * 256 + x1);
#pragma unroll
                for (int mt = 0; mt < 4; mt++)
                    mma16816h(acc[mt], a_hi[mt][ks], bh);
#pragma unroll
                for (int mt = 0; mt < 4; mt++)
                    mma16816h(acc[mt], a_hi[mt][ks], bl);
            }

            // cross-warp k-reduction (double-buffered scratch)
            float* rw = red + wid * 512;
#pragma unroll
            for (int mt = 0; mt < 4; mt++) {
                const int jl = mt * 16 + g;
                rw[(tig * 2) * 64 + jl]         = acc[mt][0];
                rw[(tig * 2 + 1) * 64 + jl]     = acc[mt][1];
                rw[(tig * 2) * 64 + jl + 8]     = acc[mt][2];
                rw[(tig * 2 + 1) * 64 + jl + 8] = acc[mt][3];
            }
            __syncthreads();          // the ONLY block sync per step

            const int e = tid * 2;
            float s0 = 0.f, s1 = 0.f;
#pragma unroll
            for (int w = 0; w < 8; w++) {
                const float2 v = *(const float2*)&red[w * 512 + e];
                s0 += v.x;
                s1 += v.y;
            }
            h0 = tanhf(s0 + xiv.x);
            h1 = tanhf(s1 + xiv.y);
        } else {
            h0 = tanhf(xiv.x);
            h1 = tanhf(xiv.y);
        }

        const size_t hoff = (size_t)t * BB * HH + (size_t)(b0 + eb) * HH + j0 + ej;
        // fp16 split: consumed by both the next step and the output GEMM
        const uint32_t fh = pack_f16(h0, h1);
        const __half2 fhv = *(const __half2*)&fh;
        const uint32_t fl = pack_f16(h0 - __half2float(fhv.x),
                                     h1 - __half2float(fhv.y));
        *(uint32_t*)&g_hfhi[hoff] = fh;
        *(uint32_t*)&g_hflo[hoff] = fl;
        if (t == SS - 1) {
            *(float2*)&g_hs[hoff] = make_float2(h0, h1);
        }

        if (t < SS - 1) {
            __syncwarp();             // this warp's h stores done
            if (lane == 0) {
                asm volatile("st.release.gpu.global.u32 [%0], %1;"
                             :: "l"(&g_wflags[((cta << 3) + wid) * 32]),
                                "r"((unsigned)(t + 1))
                             : "memory");
            }
        }
    }
}

__global__ void copy_hlast_kernel(float* __restrict__ dst)
{
    const int i = blockIdx.x * blockDim.x + threadIdx.x;
    dst[i] = g_hs[(size_t)(SS - 1) * BB * HH + i];
}

// ---------------------------------------------------------------------------
extern "C" void kernel_launch(void* const* d_in, const int* in_sizes, int n_in,
                              void* d_out, int out_size)
{
    const float* x  = (const float*)d_in[0];
    const float* Wi = (const float*)d_in[1];
    const float* bi = (const float*)d_in[2];
    const float* Wh = (const float*)d_in[3];
    const float* bh = (const float*)d_in[4];
    const float* Wo = (const float*)d_in[5];
    const float* bo = (const float*)d_in[6];
    float* out = (float*)d_out;

    cudaFuncSetAttribute(rnn_persistent_kernel,
                         cudaFuncAttributeMaxDynamicSharedMemorySize, RNN_SMEM_BYTES);
    cudaFuncSetAttribute(gemm_tc_kernel<0>,
                         cudaFuncAttributeMaxDynamicSharedMemorySize, GEMM_SMEM);
    cudaFuncSetAttribute(gemm_tc_kernel<1>,
                         cudaFuncAttributeMaxDynamicSharedMemorySize, GEMM_SMEM);

    // 0) fp32 -> fp16 splits (x: hi+lo; Wi/Wo: hi only)
    splitx_kernel<<<(BB * SS * II) / 1024, 256>>>(x);
    splitw_kernel<1><<<(HH * II) / 1024, 256>>>(Wi);
    splitw_kernel<2><<<(OO * HH) / 1024, 256>>>(Wo);

    // 1) xi = x @ Wi^T + bi + bh  (fp16x2 tensor core)
    dim3 g1((BB * SS) / 128, HH / 128);
    gemm_tc_kernel<0><<<g1, 256, GEMM_SMEM>>>(bi, bh, nullptr, II);

    // 2) recurrence (fp16x2 persistent)
    reset_wflags_kernel<<<4, 256>>>();
    rnn_persistent_kernel<<<NBLK, 256, RNN_SMEM_BYTES>>>(Wh);

    // 3) out = hs @ Wo^T + bo  (fp16x2 tensor core)
    dim3 g2((BB * SS) / 128, OO / 128);
    gemm_tc_kernel<1><<<g2, 256, GEMM_SMEM>>>(bo, nullptr, out, HH);

    // 4) h_last appended if expected
    if (out_size >= BB * SS * OO + BB * HH) {
        copy_hlast_kernel<<<(BB * HH) / 256, 256>>>(out + (size_t)BB * SS * OO);
    }
}